// round 5
// baseline (speedup 1.0000x reference)
#include <cuda_runtime.h>
#include <cstdint>

// Max-unpool 2x2 (kernel=stride=2, non-overlapping).
// x:     [N, C, H, W]   fp32
// where: [N, C, H, W]   int32 in {0..3}
// out:   [N, C, 2H, 2W] fp32
//
// R5: one thread = 4 consecutive input pixels.
//   loads : float4 x + int4 where      (2x LDG.128, dense 512B/warp each)
//   stores: 8 floats per output row    (2x STG.256 via st.global.v8.f32,
//                                       dense 1024B/warp each — sm_100+)
// Halves instruction count vs R2 while keeping all streams fully dense.

static constexpr int N = 32, C = 64, H = 64, W = 64;
static constexpr int W4 = W / 4;          // 4-pixel units per input row = 16
static constexpr int OW = 2 * W;          // output width = 128
static constexpr int ROWS = N * C * H;
static constexpr int TOTAL = ROWS * W4;   // 2,097,152 threads

__device__ __forceinline__ void stg256(float* p,
                                       float a, float b, float c, float d,
                                       float e, float f, float g, float h)
{
    asm volatile(
        "st.global.v8.f32 [%0], {%1, %2, %3, %4, %5, %6, %7, %8};"
        :: "l"(p), "f"(a), "f"(b), "f"(c), "f"(d),
           "f"(e), "f"(f), "f"(g), "f"(h)
        : "memory");
}

__global__ __launch_bounds__(256)
void unpool2x2_kernel(const float4* __restrict__ x4,
                      const int4* __restrict__ w4,
                      float* __restrict__ out)
{
    int idx = blockIdx.x * blockDim.x + threadIdx.x;
    if (idx >= TOTAL) return;

    int qw  = idx & (W4 - 1);      // unit within row (W4 = 16)
    int row = idx >> 4;            // (n,c,h)
    int h   = row & (H - 1);
    int nc  = row >> 6;

    float4 xv = x4[idx];
    int4   wv = w4[idx];

    // pixel j -> output cols 2j, 2j+1 of the 8-span
    float t0 = (wv.x == 0) ? xv.x : 0.f;
    float t1 = (wv.x == 1) ? xv.x : 0.f;
    float t2 = (wv.y == 0) ? xv.y : 0.f;
    float t3 = (wv.y == 1) ? xv.y : 0.f;
    float t4 = (wv.z == 0) ? xv.z : 0.f;
    float t5 = (wv.z == 1) ? xv.z : 0.f;
    float t6 = (wv.w == 0) ? xv.w : 0.f;
    float t7 = (wv.w == 1) ? xv.w : 0.f;

    float b0 = (wv.x == 2) ? xv.x : 0.f;
    float b1 = (wv.x == 3) ? xv.x : 0.f;
    float b2 = (wv.y == 2) ? xv.y : 0.f;
    float b3 = (wv.y == 3) ? xv.y : 0.f;
    float b4 = (wv.z == 2) ? xv.z : 0.f;
    float b5 = (wv.z == 3) ? xv.z : 0.f;
    float b6 = (wv.w == 2) ? xv.w : 0.f;
    float b7 = (wv.w == 3) ? xv.w : 0.f;

    // Output base: image nc, row 2h, col qw*8 (32B-aligned)
    size_t obase = (size_t)nc * (2 * H * OW) + (size_t)(2 * h) * OW + (size_t)qw * 8;
    stg256(out + obase,      t0, t1, t2, t3, t4, t5, t6, t7);
    stg256(out + obase + OW, b0, b1, b2, b3, b4, b5, b6, b7);
}

extern "C" void kernel_launch(void* const* d_in, const int* in_sizes, int n_in,
                              void* d_out, int out_size)
{
    const float4* x4 = (const float4*)d_in[0];
    const int4*   w4 = (const int4*)d_in[1];
    float* out = (float*)d_out;

    int threads = 256;
    int blocks = (TOTAL + threads - 1) / threads;   // 8192
    unpool2x2_kernel<<<blocks, threads>>>(x4, w4, out);
}